// round 2
// baseline (speedup 1.0000x reference)
#include <cuda_runtime.h>
#include <math.h>
#include <float.h>

#define EDIM   1024
#define HEADS  16
#define DH     64
#define BB     2
#define SS     2048
#define MTOT   (BB * SS)      // 4096
#define PAD    65             // smem row pad (words) -> conflict-free column reads

// Scratch (allocation-free rule: __device__ globals)
__device__ float g_Q[MTOT * EDIM];
__device__ float g_K[MTOT * EDIM];
__device__ float g_V[MTOT * EDIM];
__device__ float g_C[MTOT * EDIM];

// ---------------------------------------------------------------------------
// SGEMM + bias: C[M,N] = A[M,K] @ B[K,N] + bias[N]
// Fixed K = N = 1024, M = 4096. 128x128x8 tile, 256 threads, 8x8 microtile.
// ---------------------------------------------------------------------------
__global__ __launch_bounds__(256) void sgemm_bias(
    const float* __restrict__ A, const float* __restrict__ B,
    const float* __restrict__ bias, float* __restrict__ C)
{
    const int K = EDIM, N = EDIM;
    __shared__ float As[8][128];   // transposed A tile: As[k][m]
    __shared__ float Bs[8][128];   // Bs[k][n]

    const int tid = threadIdx.x;
    const int bm  = blockIdx.y * 128;
    const int bn  = blockIdx.x * 128;
    const int tx  = tid & 15;      // 0..15  -> n microtile
    const int ty  = tid >> 4;      // 0..15  -> m microtile

    const int a_row = tid >> 1;          // 0..127
    const int a_col = (tid & 1) * 4;     // 0 or 4
    const int b_row = tid >> 5;          // 0..7
    const int b_col = (tid & 31) * 4;    // 0..124

    const float* Aptr = A + (size_t)(bm + a_row) * K + a_col;
    const float* Bptr = B + (size_t)b_row * N + bn + b_col;

    float acc[8][8];
#pragma unroll
    for (int i = 0; i < 8; i++)
#pragma unroll
        for (int j = 0; j < 8; j++) acc[i][j] = 0.f;

    for (int k0 = 0; k0 < K; k0 += 8) {
        float4 av = *(const float4*)(Aptr + k0);
        float4 bv = *(const float4*)(Bptr + (size_t)k0 * N);
        __syncthreads();
        As[a_col + 0][a_row] = av.x;
        As[a_col + 1][a_row] = av.y;
        As[a_col + 2][a_row] = av.z;
        As[a_col + 3][a_row] = av.w;
        *(float4*)&Bs[b_row][b_col] = bv;
        __syncthreads();

#pragma unroll
        for (int k = 0; k < 8; k++) {
            float ar[8], br[8];
#pragma unroll
            for (int i = 0; i < 8; i++) ar[i] = As[k][ty * 8 + i];
#pragma unroll
            for (int j = 0; j < 8; j++) br[j] = Bs[k][tx * 8 + j];
#pragma unroll
            for (int i = 0; i < 8; i++)
#pragma unroll
                for (int j = 0; j < 8; j++) acc[i][j] += ar[i] * br[j];
        }
    }

    // Epilogue: + bias, vectorized stores
    const int cn = bn + tx * 8;
    float4 bias0 = *(const float4*)&bias[cn];
    float4 bias1 = *(const float4*)&bias[cn + 4];
#pragma unroll
    for (int i = 0; i < 8; i++) {
        float* crow = C + (size_t)(bm + ty * 8 + i) * N + cn;
        float4 v0 = make_float4(acc[i][0] + bias0.x, acc[i][1] + bias0.y,
                                acc[i][2] + bias0.z, acc[i][3] + bias0.w);
        float4 v1 = make_float4(acc[i][4] + bias1.x, acc[i][5] + bias1.y,
                                acc[i][6] + bias1.z, acc[i][7] + bias1.w);
        *(float4*)crow       = v0;
        *(float4*)(crow + 4) = v1;
    }
}

// ---------------------------------------------------------------------------
// Flash attention (fp32, online softmax).
// Grid: (S/64, B*H), 256 threads (8 warps). Warp w owns query rows [8w, 8w+8);
// lane owns head-dim / key columns {lane, lane+32}.
// ---------------------------------------------------------------------------
__global__ __launch_bounds__(256) void attn_kernel(
    const float* __restrict__ Q, const float* __restrict__ Kg,
    const float* __restrict__ Vg, float* __restrict__ O)
{
    extern __shared__ float sm[];
    float* Qs = sm;                 // 64 x PAD
    float* Ks = sm + 64 * PAD;      // 64 x PAD  (rows = key idx, cols = dh)
    float* Vs = sm + 2 * 64 * PAD;  // 64 x PAD  (rows = key idx, cols = dh)
    float* Ps = sm + 3 * 64 * PAD;  // 64 x PAD  (rows = query,  cols = key)

    const int tid  = threadIdx.x;
    const int lane = tid & 31;
    const int warp = tid >> 5;
    const int qt   = blockIdx.x;          // query tile 0..31
    const int bh   = blockIdx.y;          // 0..31
    const int b    = bh >> 4;
    const int h    = bh & 15;
    const int q0   = qt * 64;
    const size_t base = (size_t)b * SS * EDIM + (size_t)h * DH;

    // Load Q tile (64 x 64)
    for (int i = tid; i < 64 * 16; i += 256) {       // 1024 float4 slots
        int r = i >> 4;
        int c = (i & 15) * 4;
        float4 v = *(const float4*)&Q[base + (size_t)(q0 + r) * EDIM + c];
        float* p = &Qs[r * PAD + c];
        p[0] = v.x; p[1] = v.y; p[2] = v.z; p[3] = v.w;
    }

    float o0[8], o1[8], mrow[8], lrow[8];
#pragma unroll
    for (int i = 0; i < 8; i++) { o0[i] = 0.f; o1[i] = 0.f; mrow[i] = -FLT_MAX; lrow[i] = 0.f; }
    const int wr = warp * 8;

    for (int kt = 0; kt < SS / 64; kt++) {
        __syncthreads();   // previous iteration's Vs/Ps reads done
        const int k0 = kt * 64;
        for (int i = tid; i < 64 * 16; i += 256) {
            int r = i >> 4;
            int c = (i & 15) * 4;
            size_t g = base + (size_t)(k0 + r) * EDIM + c;
            float4 kv = *(const float4*)&Kg[g];
            float4 vv = *(const float4*)&Vg[g];
            float* pk = &Ks[r * PAD + c];
            float* pv = &Vs[r * PAD + c];
            pk[0] = kv.x; pk[1] = kv.y; pk[2] = kv.z; pk[3] = kv.w;
            pv[0] = vv.x; pv[1] = vv.y; pv[2] = vv.z; pv[3] = vv.w;
        }
        __syncthreads();

        // Scores: s[r][c] = dot(Q[r], K[c]) ; lane cols c0=lane, c1=lane+32
        float s0[8], s1[8];
#pragma unroll
        for (int i = 0; i < 8; i++) { s0[i] = 0.f; s1[i] = 0.f; }
#pragma unroll 2
        for (int kk = 0; kk < 64; kk++) {
            float k0v = Ks[lane * PAD + kk];
            float k1v = Ks[(lane + 32) * PAD + kk];
#pragma unroll
            for (int i = 0; i < 8; i++) {
                float qv = Qs[(wr + i) * PAD + kk];
                s0[i] += qv * k0v;
                s1[i] += qv * k1v;
            }
        }

        // Online softmax (per row, warp-wide)
        const float sc = 0.125f;   // 1/sqrt(64)
#pragma unroll
        for (int i = 0; i < 8; i++) {
            s0[i] *= sc; s1[i] *= sc;
            float v = fmaxf(s0[i], s1[i]);
#pragma unroll
            for (int off = 16; off > 0; off >>= 1)
                v = fmaxf(v, __shfl_xor_sync(0xffffffffu, v, off));
            float mn = fmaxf(mrow[i], v);
            float f  = __expf(mrow[i] - mn);
            float p0 = __expf(s0[i] - mn);
            float p1 = __expf(s1[i] - mn);
            float rs = p0 + p1;
#pragma unroll
            for (int off = 16; off > 0; off >>= 1)
                rs += __shfl_xor_sync(0xffffffffu, rs, off);
            lrow[i] = lrow[i] * f + rs;
            mrow[i] = mn;
            o0[i] *= f; o1[i] *= f;
            Ps[(wr + i) * PAD + lane]      = p0;
            Ps[(wr + i) * PAD + lane + 32] = p1;
        }
        __syncwarp();

        // O += P @ V
#pragma unroll 2
        for (int kk = 0; kk < 64; kk++) {
            float v0 = Vs[kk * PAD + lane];
            float v1 = Vs[kk * PAD + lane + 32];
#pragma unroll
            for (int i = 0; i < 8; i++) {
                float p = Ps[(wr + i) * PAD + kk];
                o0[i] += p * v0;
                o1[i] += p * v1;
            }
        }
    }

    // Epilogue: normalize, write context
#pragma unroll
    for (int i = 0; i < 8; i++) {
        float inv = 1.0f / lrow[i];
        float* orow = O + base + (size_t)(q0 + wr + i) * EDIM;
        orow[lane]      = o0[i] * inv;
        orow[lane + 32] = o1[i] * inv;
    }
}

// ---------------------------------------------------------------------------
// Launch: 3 QKV GEMMs -> attention -> output GEMM. All graph-capturable.
// ---------------------------------------------------------------------------
extern "C" void kernel_launch(void* const* d_in, const int* in_sizes, int n_in,
                              void* d_out, int out_size)
{
    const float* x  = (const float*)d_in[0];
    const float* Wq = (const float*)d_in[1];
    const float* bq = (const float*)d_in[2];
    const float* Wk = (const float*)d_in[3];
    const float* bk = (const float*)d_in[4];
    const float* Wv = (const float*)d_in[5];
    const float* bv = (const float*)d_in[6];
    const float* Wo = (const float*)d_in[7];
    const float* bo = (const float*)d_in[8];
    float* out = (float*)d_out;

    float *qp, *kp, *vp, *cp;
    cudaGetSymbolAddress((void**)&qp, g_Q);
    cudaGetSymbolAddress((void**)&kp, g_K);
    cudaGetSymbolAddress((void**)&vp, g_V);
    cudaGetSymbolAddress((void**)&cp, g_C);

    dim3 gg(EDIM / 128, MTOT / 128);   // (8, 32)
    sgemm_bias<<<gg, 256>>>(x, Wq, bq, qp);
    sgemm_bias<<<gg, 256>>>(x, Wk, bk, kp);
    sgemm_bias<<<gg, 256>>>(x, Wv, bv, vp);

    size_t smem = (size_t)4 * 64 * PAD * sizeof(float);   // 66560 B
    cudaFuncSetAttribute(attn_kernel, cudaFuncAttributeMaxDynamicSharedMemorySize, (int)smem);
    attn_kernel<<<dim3(SS / 64, BB * HEADS), 256, smem>>>(qp, kp, vp, cp);

    sgemm_bias<<<gg, 256>>>(cp, Wo, bo, out);
}

// round 3
// speedup vs baseline: 1.0019x; 1.0019x over previous
#include <cuda_runtime.h>
#include <math.h>
#include <float.h>

#define EDIM   1024
#define HEADS  16
#define DH     64
#define BB     2
#define SS     2048
#define MTOT   (BB * SS)      // 4096
#define PAD    65             // smem row pad (words) -> conflict-free column reads

// Scratch (allocation-free rule: __device__ globals)
__device__ float g_Q[MTOT * EDIM];
__device__ float g_K[MTOT * EDIM];
__device__ float g_V[MTOT * EDIM];
__device__ float g_C[MTOT * EDIM];

// ---------------------------------------------------------------------------
// SGEMM + bias: C[M,N] = A[M,K] @ B[K,N] + bias[N]
// Fixed K = N = 1024, M = 4096. 128x128x8 tile, 256 threads, 8x8 microtile.
// ---------------------------------------------------------------------------
__global__ __launch_bounds__(256) void sgemm_bias(
    const float* __restrict__ A, const float* __restrict__ B,
    const float* __restrict__ bias, float* __restrict__ C)
{
    const int K = EDIM, N = EDIM;
    __shared__ float As[8][128];   // transposed A tile: As[k][m]
    __shared__ float Bs[8][128];   // Bs[k][n]

    const int tid = threadIdx.x;
    const int bm  = blockIdx.y * 128;
    const int bn  = blockIdx.x * 128;
    const int tx  = tid & 15;      // 0..15  -> n microtile
    const int ty  = tid >> 4;      // 0..15  -> m microtile

    const int a_row = tid >> 1;          // 0..127
    const int a_col = (tid & 1) * 4;     // 0 or 4
    const int b_row = tid >> 5;          // 0..7
    const int b_col = (tid & 31) * 4;    // 0..124

    const float* Aptr = A + (size_t)(bm + a_row) * K + a_col;
    const float* Bptr = B + (size_t)b_row * N + bn + b_col;

    float acc[8][8];
#pragma unroll
    for (int i = 0; i < 8; i++)
#pragma unroll
        for (int j = 0; j < 8; j++) acc[i][j] = 0.f;

    for (int k0 = 0; k0 < K; k0 += 8) {
        float4 av = *(const float4*)(Aptr + k0);
        float4 bv = *(const float4*)(Bptr + (size_t)k0 * N);
        __syncthreads();
        As[a_col + 0][a_row] = av.x;
        As[a_col + 1][a_row] = av.y;
        As[a_col + 2][a_row] = av.z;
        As[a_col + 3][a_row] = av.w;
        *(float4*)&Bs[b_row][b_col] = bv;
        __syncthreads();

#pragma unroll
        for (int k = 0; k < 8; k++) {
            float ar[8], br[8];
#pragma unroll
            for (int i = 0; i < 8; i++) ar[i] = As[k][ty * 8 + i];
#pragma unroll
            for (int j = 0; j < 8; j++) br[j] = Bs[k][tx * 8 + j];
#pragma unroll
            for (int i = 0; i < 8; i++)
#pragma unroll
                for (int j = 0; j < 8; j++) acc[i][j] += ar[i] * br[j];
        }
    }

    // Epilogue: + bias, vectorized stores
    const int cn = bn + tx * 8;
    float4 bias0 = *(const float4*)&bias[cn];
    float4 bias1 = *(const float4*)&bias[cn + 4];
#pragma unroll
    for (int i = 0; i < 8; i++) {
        float* crow = C + (size_t)(bm + ty * 8 + i) * N + cn;
        float4 v0 = make_float4(acc[i][0] + bias0.x, acc[i][1] + bias0.y,
                                acc[i][2] + bias0.z, acc[i][3] + bias0.w);
        float4 v1 = make_float4(acc[i][4] + bias1.x, acc[i][5] + bias1.y,
                                acc[i][6] + bias1.z, acc[i][7] + bias1.w);
        *(float4*)crow       = v0;
        *(float4*)(crow + 4) = v1;
    }
}

// ---------------------------------------------------------------------------
// Flash attention (fp32, online softmax).
// Grid: (S/64, B*H), 256 threads (8 warps). Warp w owns query rows [8w, 8w+8);
// lane owns head-dim / key columns {lane, lane+32}.
// ---------------------------------------------------------------------------
__global__ __launch_bounds__(256) void attn_kernel(
    const float* __restrict__ Q, const float* __restrict__ Kg,
    const float* __restrict__ Vg, float* __restrict__ O)
{
    extern __shared__ float sm[];
    float* Qs = sm;                 // 64 x PAD
    float* Ks = sm + 64 * PAD;      // 64 x PAD  (rows = key idx, cols = dh)
    float* Vs = sm + 2 * 64 * PAD;  // 64 x PAD  (rows = key idx, cols = dh)
    float* Ps = sm + 3 * 64 * PAD;  // 64 x PAD  (rows = query,  cols = key)

    const int tid  = threadIdx.x;
    const int lane = tid & 31;
    const int warp = tid >> 5;
    const int qt   = blockIdx.x;          // query tile 0..31
    const int bh   = blockIdx.y;          // 0..31
    const int b    = bh >> 4;
    const int h    = bh & 15;
    const int q0   = qt * 64;
    const size_t base = (size_t)b * SS * EDIM + (size_t)h * DH;

    // Load Q tile (64 x 64)
    for (int i = tid; i < 64 * 16; i += 256) {       // 1024 float4 slots
        int r = i >> 4;
        int c = (i & 15) * 4;
        float4 v = *(const float4*)&Q[base + (size_t)(q0 + r) * EDIM + c];
        float* p = &Qs[r * PAD + c];
        p[0] = v.x; p[1] = v.y; p[2] = v.z; p[3] = v.w;
    }

    float o0[8], o1[8], mrow[8], lrow[8];
#pragma unroll
    for (int i = 0; i < 8; i++) { o0[i] = 0.f; o1[i] = 0.f; mrow[i] = -FLT_MAX; lrow[i] = 0.f; }
    const int wr = warp * 8;

    for (int kt = 0; kt < SS / 64; kt++) {
        __syncthreads();   // previous iteration's Vs/Ps reads done
        const int k0 = kt * 64;
        for (int i = tid; i < 64 * 16; i += 256) {
            int r = i >> 4;
            int c = (i & 15) * 4;
            size_t g = base + (size_t)(k0 + r) * EDIM + c;
            float4 kv = *(const float4*)&Kg[g];
            float4 vv = *(const float4*)&Vg[g];
            float* pk = &Ks[r * PAD + c];
            float* pv = &Vs[r * PAD + c];
            pk[0] = kv.x; pk[1] = kv.y; pk[2] = kv.z; pk[3] = kv.w;
            pv[0] = vv.x; pv[1] = vv.y; pv[2] = vv.z; pv[3] = vv.w;
        }
        __syncthreads();

        // Scores: s[r][c] = dot(Q[r], K[c]) ; lane cols c0=lane, c1=lane+32
        float s0[8], s1[8];
#pragma unroll
        for (int i = 0; i < 8; i++) { s0[i] = 0.f; s1[i] = 0.f; }
#pragma unroll 2
        for (int kk = 0; kk < 64; kk++) {
            float k0v = Ks[lane * PAD + kk];
            float k1v = Ks[(lane + 32) * PAD + kk];
#pragma unroll
            for (int i = 0; i < 8; i++) {
                float qv = Qs[(wr + i) * PAD + kk];
                s0[i] += qv * k0v;
                s1[i] += qv * k1v;
            }
        }

        // Online softmax (per row, warp-wide)
        const float sc = 0.125f;   // 1/sqrt(64)
#pragma unroll
        for (int i = 0; i < 8; i++) {
            s0[i] *= sc; s1[i] *= sc;
            float v = fmaxf(s0[i], s1[i]);
#pragma unroll
            for (int off = 16; off > 0; off >>= 1)
                v = fmaxf(v, __shfl_xor_sync(0xffffffffu, v, off));
            float mn = fmaxf(mrow[i], v);
            float f  = __expf(mrow[i] - mn);
            float p0 = __expf(s0[i] - mn);
            float p1 = __expf(s1[i] - mn);
            float rs = p0 + p1;
#pragma unroll
            for (int off = 16; off > 0; off >>= 1)
                rs += __shfl_xor_sync(0xffffffffu, rs, off);
            lrow[i] = lrow[i] * f + rs;
            mrow[i] = mn;
            o0[i] *= f; o1[i] *= f;
            Ps[(wr + i) * PAD + lane]      = p0;
            Ps[(wr + i) * PAD + lane + 32] = p1;
        }
        __syncwarp();

        // O += P @ V
#pragma unroll 2
        for (int kk = 0; kk < 64; kk++) {
            float v0 = Vs[kk * PAD + lane];
            float v1 = Vs[kk * PAD + lane + 32];
#pragma unroll
            for (int i = 0; i < 8; i++) {
                float p = Ps[(wr + i) * PAD + kk];
                o0[i] += p * v0;
                o1[i] += p * v1;
            }
        }
    }

    // Epilogue: normalize, write context
#pragma unroll
    for (int i = 0; i < 8; i++) {
        float inv = 1.0f / lrow[i];
        float* orow = O + base + (size_t)(q0 + wr + i) * EDIM;
        orow[lane]      = o0[i] * inv;
        orow[lane + 32] = o1[i] * inv;
    }
}

// ---------------------------------------------------------------------------
// Launch: 3 QKV GEMMs -> attention -> output GEMM. All graph-capturable.
// ---------------------------------------------------------------------------
extern "C" void kernel_launch(void* const* d_in, const int* in_sizes, int n_in,
                              void* d_out, int out_size)
{
    const float* x  = (const float*)d_in[0];
    const float* Wq = (const float*)d_in[1];
    const float* bq = (const float*)d_in[2];
    const float* Wk = (const float*)d_in[3];
    const float* bk = (const float*)d_in[4];
    const float* Wv = (const float*)d_in[5];
    const float* bv = (const float*)d_in[6];
    const float* Wo = (const float*)d_in[7];
    const float* bo = (const float*)d_in[8];
    float* out = (float*)d_out;

    float *qp, *kp, *vp, *cp;
    cudaGetSymbolAddress((void**)&qp, g_Q);
    cudaGetSymbolAddress((void**)&kp, g_K);
    cudaGetSymbolAddress((void**)&vp, g_V);
    cudaGetSymbolAddress((void**)&cp, g_C);

    dim3 gg(EDIM / 128, MTOT / 128);   // (8, 32)
    sgemm_bias<<<gg, 256>>>(x, Wq, bq, qp);
    sgemm_bias<<<gg, 256>>>(x, Wk, bk, kp);
    sgemm_bias<<<gg, 256>>>(x, Wv, bv, vp);

    size_t smem = (size_t)4 * 64 * PAD * sizeof(float);   // 66560 B
    cudaFuncSetAttribute(attn_kernel, cudaFuncAttributeMaxDynamicSharedMemorySize, (int)smem);
    attn_kernel<<<dim3(SS / 64, BB * HEADS), 256, smem>>>(qp, kp, vp, cp);

    sgemm_bias<<<gg, 256>>>(cp, Wo, bo, out);
}